// round 2
// baseline (speedup 1.0000x reference)
#include <cuda_runtime.h>
#include <math.h>

// Problem constants
#define B_ 128
#define T_ 512
#define C_ 512
#define TC_ (T_ * C_)          // 262144
#define M_ (B_ * T_)           // 65536
#define H_ (2 * C_)            // 1024
#define EPS_ 1e-5f

// ---------------- scratch (static device arrays; no allocation) ----------------
__device__ float g_x [(size_t)B_ * TC_];   // ln1 output
__device__ float g_z [(size_t)B_ * TC_];   // triu-mix + inputs (ln2 input)
__device__ float g_x2[(size_t)B_ * TC_];   // ln2 output
__device__ float g_h [(size_t)M_ * H_];    // gelu(fc1) activations
__device__ float g_mu  [2 * B_];
__device__ float g_rstd[2 * B_];

// ---------------- per-batch joint (T,C) layernorm stats ----------------
// which==0: read from src (the harness input). which==1: read from g_z.
__global__ void stats_kernel(const float* __restrict__ src, int which) {
    int b   = blockIdx.x;
    int tid = threadIdx.x;
    const float* base = (which == 0) ? src : g_z;
    const float4* p = reinterpret_cast<const float4*>(base + (size_t)b * TC_);
    float sx = 0.f, sy = 0.f, sz = 0.f, sw = 0.f;
    float qx = 0.f, qy = 0.f, qz = 0.f, qw = 0.f;
    for (int i = tid; i < TC_ / 4; i += 256) {
        float4 v = p[i];
        sx += v.x; sy += v.y; sz += v.z; sw += v.w;
        qx = fmaf(v.x, v.x, qx);
        qy = fmaf(v.y, v.y, qy);
        qz = fmaf(v.z, v.z, qz);
        qw = fmaf(v.w, v.w, qw);
    }
    __shared__ double sh [256];
    __shared__ double sh2[256];
    sh [tid] = (double)sx + (double)sy + (double)sz + (double)sw;
    sh2[tid] = (double)qx + (double)qy + (double)qz + (double)qw;
    __syncthreads();
    for (int off = 128; off > 0; off >>= 1) {
        if (tid < off) { sh[tid] += sh[tid + off]; sh2[tid] += sh2[tid + off]; }
        __syncthreads();
    }
    if (tid == 0) {
        double m   = sh[0]  / (double)TC_;
        double var = sh2[0] / (double)TC_ - m * m;
        g_mu  [which * B_ + b] = (float)m;
        g_rstd[which * B_ + b] = (float)(1.0 / sqrt(var + (double)EPS_));
    }
}

// ---------------- ln1 apply: g_x = (inp - mu0) * rstd0 * w + b ----------------
__global__ void apply_ln1(const float* __restrict__ src,
                          const float* __restrict__ w,
                          const float* __restrict__ bias) {
    int i = blockIdx.x * blockDim.x + threadIdx.x;   // float4 index
    int total = B_ * TC_ / 4;
    if (i >= total) return;
    int b = i / (TC_ / 4);
    int r = i % (TC_ / 4);
    float mu = g_mu[b];
    float rs = g_rstd[b];
    float4 v  = reinterpret_cast<const float4*>(src)[i];
    float4 wv = reinterpret_cast<const float4*>(w)[r];
    float4 bv = reinterpret_cast<const float4*>(bias)[r];
    v.x = fmaf((v.x - mu) * rs, wv.x, bv.x);
    v.y = fmaf((v.y - mu) * rs, wv.y, bv.y);
    v.z = fmaf((v.z - mu) * rs, wv.z, bv.z);
    v.w = fmaf((v.w - mu) * rs, wv.w, bv.w);
    reinterpret_cast<float4*>(g_x)[i] = v;
}

// ---------------- ln2 apply: g_x2 = (g_z - mu1) * rstd1 * w + b ----------------
__global__ void apply_ln2(const float* __restrict__ w,
                          const float* __restrict__ bias) {
    int i = blockIdx.x * blockDim.x + threadIdx.x;
    int total = B_ * TC_ / 4;
    if (i >= total) return;
    int b = i / (TC_ / 4);
    int r = i % (TC_ / 4);
    float mu = g_mu[B_ + b];
    float rs = g_rstd[B_ + b];
    float4 v  = reinterpret_cast<const float4*>(g_z)[i];
    float4 wv = reinterpret_cast<const float4*>(w)[r];
    float4 bv = reinterpret_cast<const float4*>(bias)[r];
    v.x = fmaf((v.x - mu) * rs, wv.x, bv.x);
    v.y = fmaf((v.y - mu) * rs, wv.y, bv.y);
    v.z = fmaf((v.z - mu) * rs, wv.z, bv.z);
    v.w = fmaf((v.w - mu) * rs, wv.w, bv.w);
    reinterpret_cast<float4*>(g_x2)[i] = v;
}

// ---------------- batched causal TriU mix:
// g_z[b,s,c] = sum_{t<=s} W[s,t] * g_x[b,t,c] + triu_b[s] + inputs[b,s,c]
// A = W [T,T] row-major (k-contig, NN), B = g_x[b] [T,C] (n-contig, NN)
__global__ void __launch_bounds__(256, 2)
gemm_triu(const float* __restrict__ W, const float* __restrict__ tb,
          const float* __restrict__ inp) {
    int bx = blockIdx.x, by = blockIdx.y, bz = blockIdx.z;
    const float* X = g_x + (size_t)bz * TC_;
    const float* I = inp + (size_t)bz * TC_;
    float*       Z = g_z + (size_t)bz * TC_;

    __shared__ float As[8][128];
    __shared__ float Bs[8][128];

    int tid = threadIdx.x;
    int tm = tid >> 4, tn = tid & 15;

    float acc[8][8];
#pragma unroll
    for (int i = 0; i < 8; ++i)
#pragma unroll
        for (int j = 0; j < 8; ++j) acc[i][j] = 0.f;

    int arow_l = tid >> 1;                 // 0..127
    int arow   = by * 128 + arow_l;        // global s
    int acol4  = (tid & 1) * 4;            // 0 or 4
    int bk_l   = tid >> 5;                 // 0..7
    int bcol_l = (tid & 31) * 4;           // 0..124
    int bcol   = bx * 128 + bcol_l;

    int ktiles = (by + 1) * 16;            // triangular early-exit

    for (int kt = 0; kt < ktiles; ++kt) {
        int k0 = kt * 8;
        // A tile (masked tril)
        float4 a = *reinterpret_cast<const float4*>(W + (size_t)arow * T_ + k0 + acol4);
        int kb = k0 + acol4;
        if (kb + 0 > arow) a.x = 0.f;
        if (kb + 1 > arow) a.y = 0.f;
        if (kb + 2 > arow) a.z = 0.f;
        if (kb + 3 > arow) a.w = 0.f;
        As[acol4 + 0][arow_l] = a.x;
        As[acol4 + 1][arow_l] = a.y;
        As[acol4 + 2][arow_l] = a.z;
        As[acol4 + 3][arow_l] = a.w;
        // B tile (n-contiguous)
        float4 bvec = *reinterpret_cast<const float4*>(X + (size_t)(k0 + bk_l) * C_ + bcol);
        *reinterpret_cast<float4*>(&Bs[bk_l][bcol_l]) = bvec;
        __syncthreads();
#pragma unroll
        for (int kk = 0; kk < 8; ++kk) {
            float af[8], bf[8];
            *reinterpret_cast<float4*>(&af[0]) = *reinterpret_cast<const float4*>(&As[kk][tm * 8]);
            *reinterpret_cast<float4*>(&af[4]) = *reinterpret_cast<const float4*>(&As[kk][tm * 8 + 4]);
            *reinterpret_cast<float4*>(&bf[0]) = *reinterpret_cast<const float4*>(&Bs[kk][tn * 8]);
            *reinterpret_cast<float4*>(&bf[4]) = *reinterpret_cast<const float4*>(&Bs[kk][tn * 8 + 4]);
#pragma unroll
            for (int i = 0; i < 8; ++i)
#pragma unroll
                for (int j = 0; j < 8; ++j)
                    acc[i][j] = fmaf(af[i], bf[j], acc[i][j]);
        }
        __syncthreads();
    }

#pragma unroll
    for (int i = 0; i < 8; ++i) {
        int m = by * 128 + tm * 8 + i;
        float add = tb[m];
#pragma unroll
        for (int j = 0; j < 8; ++j) {
            int n = bx * 128 + tn * 8 + j;
            size_t idx = (size_t)m * C_ + n;
            Z[idx] = acc[i][j] + add + I[idx];
        }
    }
}

// ---------------- fc1: g_h = gelu(g_x2 @ fc1_W^T + fc1_b)  (NT gemm)
// A = g_x2 [M_, C_] (k-contig), B = fc1_W [H_, C_] (k-contig)
__global__ void __launch_bounds__(256, 2)
gemm_fc1(const float* __restrict__ Wt, const float* __restrict__ b1) {
    int bx = blockIdx.x, by = blockIdx.y;
    __shared__ float As[8][128];
    __shared__ float Bs[8][128];
    int tid = threadIdx.x;
    int tm = tid >> 4, tn = tid & 15;

    float acc[8][8];
#pragma unroll
    for (int i = 0; i < 8; ++i)
#pragma unroll
        for (int j = 0; j < 8; ++j) acc[i][j] = 0.f;

    int row_l = tid >> 1;
    int col4  = (tid & 1) * 4;
    int arow  = by * 128 + row_l;          // global m
    int brow  = bx * 128 + row_l;          // global n

    for (int kt = 0; kt < C_ / 8; ++kt) {
        int k0 = kt * 8;
        float4 a = *reinterpret_cast<const float4*>(g_x2 + (size_t)arow * C_ + k0 + col4);
        As[col4 + 0][row_l] = a.x;
        As[col4 + 1][row_l] = a.y;
        As[col4 + 2][row_l] = a.z;
        As[col4 + 3][row_l] = a.w;
        float4 b = *reinterpret_cast<const float4*>(Wt + (size_t)brow * C_ + k0 + col4);
        Bs[col4 + 0][row_l] = b.x;
        Bs[col4 + 1][row_l] = b.y;
        Bs[col4 + 2][row_l] = b.z;
        Bs[col4 + 3][row_l] = b.w;
        __syncthreads();
#pragma unroll
        for (int kk = 0; kk < 8; ++kk) {
            float af[8], bf[8];
            *reinterpret_cast<float4*>(&af[0]) = *reinterpret_cast<const float4*>(&As[kk][tm * 8]);
            *reinterpret_cast<float4*>(&af[4]) = *reinterpret_cast<const float4*>(&As[kk][tm * 8 + 4]);
            *reinterpret_cast<float4*>(&bf[0]) = *reinterpret_cast<const float4*>(&Bs[kk][tn * 8]);
            *reinterpret_cast<float4*>(&bf[4]) = *reinterpret_cast<const float4*>(&Bs[kk][tn * 8 + 4]);
#pragma unroll
            for (int i = 0; i < 8; ++i)
#pragma unroll
                for (int j = 0; j < 8; ++j)
                    acc[i][j] = fmaf(af[i], bf[j], acc[i][j]);
        }
        __syncthreads();
    }

#pragma unroll
    for (int i = 0; i < 8; ++i) {
        int m = by * 128 + tm * 8 + i;
#pragma unroll
        for (int j = 0; j < 8; ++j) {
            int n = bx * 128 + tn * 8 + j;
            float v = acc[i][j] + b1[n];
            // exact GELU
            v = 0.5f * v * (1.0f + erff(v * 0.70710678118654752f));
            g_h[(size_t)m * H_ + n] = v;
        }
    }
}

// ---------------- fc2: out = g_h @ fc2_W^T + fc2_b + g_x2  (NT gemm)
// A = g_h [M_, H_] (k-contig), B = fc2_W [C_, H_] (k-contig)
__global__ void __launch_bounds__(256, 2)
gemm_fc2(const float* __restrict__ Wt, const float* __restrict__ b2,
         float* __restrict__ out) {
    int bx = blockIdx.x, by = blockIdx.y;
    __shared__ float As[8][128];
    __shared__ float Bs[8][128];
    int tid = threadIdx.x;
    int tm = tid >> 4, tn = tid & 15;

    float acc[8][8];
#pragma unroll
    for (int i = 0; i < 8; ++i)
#pragma unroll
        for (int j = 0; j < 8; ++j) acc[i][j] = 0.f;

    int row_l = tid >> 1;
    int col4  = (tid & 1) * 4;
    int arow  = by * 128 + row_l;
    int brow  = bx * 128 + row_l;

    for (int kt = 0; kt < H_ / 8; ++kt) {
        int k0 = kt * 8;
        float4 a = *reinterpret_cast<const float4*>(g_h + (size_t)arow * H_ + k0 + col4);
        As[col4 + 0][row_l] = a.x;
        As[col4 + 1][row_l] = a.y;
        As[col4 + 2][row_l] = a.z;
        As[col4 + 3][row_l] = a.w;
        float4 b = *reinterpret_cast<const float4*>(Wt + (size_t)brow * H_ + k0 + col4);
        Bs[col4 + 0][row_l] = b.x;
        Bs[col4 + 1][row_l] = b.y;
        Bs[col4 + 2][row_l] = b.z;
        Bs[col4 + 3][row_l] = b.w;
        __syncthreads();
#pragma unroll
        for (int kk = 0; kk < 8; ++kk) {
            float af[8], bf[8];
            *reinterpret_cast<float4*>(&af[0]) = *reinterpret_cast<const float4*>(&As[kk][tm * 8]);
            *reinterpret_cast<float4*>(&af[4]) = *reinterpret_cast<const float4*>(&As[kk][tm * 8 + 4]);
            *reinterpret_cast<float4*>(&bf[0]) = *reinterpret_cast<const float4*>(&Bs[kk][tn * 8]);
            *reinterpret_cast<float4*>(&bf[4]) = *reinterpret_cast<const float4*>(&Bs[kk][tn * 8 + 4]);
#pragma unroll
            for (int i = 0; i < 8; ++i)
#pragma unroll
                for (int j = 0; j < 8; ++j)
                    acc[i][j] = fmaf(af[i], bf[j], acc[i][j]);
        }
        __syncthreads();
    }

#pragma unroll
    for (int i = 0; i < 8; ++i) {
        int m = by * 128 + tm * 8 + i;
#pragma unroll
        for (int j = 0; j < 8; ++j) {
            int n = bx * 128 + tn * 8 + j;
            size_t idx = (size_t)m * C_ + n;
            out[idx] = acc[i][j] + b2[n] + g_x2[idx];
        }
    }
}

// ---------------- launch ----------------
extern "C" void kernel_launch(void* const* d_in, const int* in_sizes, int n_in,
                              void* d_out, int out_size) {
    (void)in_sizes; (void)n_in; (void)out_size;
    const float* inp    = (const float*)d_in[0];
    const float* ln1_w  = (const float*)d_in[1];
    const float* ln1_b  = (const float*)d_in[2];
    const float* ln2_w  = (const float*)d_in[3];
    const float* ln2_b  = (const float*)d_in[4];
    const float* triu_W = (const float*)d_in[5];
    const float* triu_b = (const float*)d_in[6];
    const float* fc1_W  = (const float*)d_in[7];
    const float* fc1_b  = (const float*)d_in[8];
    const float* fc2_W  = (const float*)d_in[9];
    const float* fc2_b  = (const float*)d_in[10];
    float* out = (float*)d_out;

    int ew_blocks = (B_ * TC_ / 4 + 255) / 256;

    // 1. ln1: stats over inputs, apply -> g_x
    stats_kernel<<<B_, 256>>>(inp, 0);
    apply_ln1<<<ew_blocks, 256>>>(inp, ln1_w, ln1_b);

    // 2. TriU causal mix (+bias +residual inputs) -> g_z
    gemm_triu<<<dim3(C_ / 128, T_ / 128, B_), 256>>>(triu_W, triu_b, inp);

    // 3. ln2: stats over g_z, apply -> g_x2
    stats_kernel<<<B_, 256>>>(inp /*unused for which=1*/, 1);
    apply_ln2<<<ew_blocks, 256>>>(ln2_w, ln2_b);

    // 4. fc1 + exact GELU -> g_h
    gemm_fc1<<<dim3(H_ / 128, M_ / 128), 256>>>(fc1_W, fc1_b);

    // 5. fc2 + bias + residual(g_x2) -> out
    gemm_fc2<<<dim3(C_ / 128, M_ / 128), 256>>>(fc2_W, fc2_b, out);
}